// round 12
// baseline (speedup 1.0000x reference)
#include <cuda_runtime.h>
#include <cstdint>

// Retrace_9844065042706 — affine-segment scan, cp.async staging (split kernels).
// Pass1: block = 2 b x 16 d over a 32-step segment, 32 threads, 21.4KB smem
// -> 10 resident blocks/SM. Copy fully strength-reduced (20 unrolled cp16).
// Pass2: 8 lanes/chain: 2 segments serial-fold + 3-step width-8 shuffle tree.

#define RB 2048
#define RT 512
#define RD 16
#define SEG 16
#define SEGLEN 32
#define NJ (RT - 1)            // 511
#define BD (RB * RD)           // 32768 chains
#define NBL 2                  // b's per block
#define NTH 32                 // threads (2 b x 16 d)
#define NBG (RB / NBL)         // 1024 b-groups

// smem (floats): 5 tensors [2][32][16] (+16 pad per b), then bp [2][33]
#define BSTR  528
#define TS    (NBL * BSTR)     // 1056
#define BPOFF (5 * TS)         // 5280
#define BPSTR 33
#define SMEM_FLOATS (BPOFF + NBL * BPSTR)   // 5346 -> 21384 B
#define SMEM_BYTES  (SMEM_FLOATS * 4)

static constexpr float GAMMA = 0.99f;

// Dense scratch, seg-major (chain-contiguous): 10 MB
__device__ float4 g4 [(size_t)SEG * BD];   // {A, M, beta, delta}
__device__ float  gal[(size_t)SEG * BD];   // alpha

__device__ __forceinline__ void cp16(uint32_t s, const void* g) {
    asm volatile("cp.async.cg.shared.global [%0], [%1], 16;" :: "r"(s), "l"(g));
}
__device__ __forceinline__ void cp4(uint32_t s, const void* g) {
    asm volatile("cp.async.ca.shared.global [%0], [%1], 4;" :: "r"(s), "l"(g));
}
__device__ __forceinline__ void cp_commit() { asm volatile("cp.async.commit_group;"); }
template <int N>
__device__ __forceinline__ void cp_wait() {
    asm volatile("cp.async.wait_group %0;" :: "n"(N));
}
__device__ __forceinline__ uint32_t smem_u32(const void* p) {
    return (uint32_t)__cvta_generic_to_shared(p);
}

// Stage rows [k0, k0+16): thread tid covers k in {k0+(tid>>2), k0+(tid>>2)+8},
// d4 = tid&3, both b's. 20 cp16 + 1 cp4, addresses precomputed.
__device__ __forceinline__ void copy_half(
    float* sm, int tid, int bg, int lo, int k0,
    const float* __restrict__ E, const float* __restrict__ TQ,
    const float* __restrict__ TPP, const float* __restrict__ R,
    const float* __restrict__ Q, const float* __restrict__ BPP)
{
    const uint32_t sbase = smem_u32(sm);
    const int kA  = k0 + (tid >> 2);          // k0..k0+7
    const int kB  = kA + 8;                   // k0+8..k0+15
    const int d4f = (tid & 3) * 4;            // float offset within row
    const int t1A = min(lo + 1 + kA, RT - 1); // rows for E, TQ, TPP
    const int t1B = min(lo + 1 + kB, RT - 1);
    const int t0A = lo + kA;                  // rows for R, Q
    const int t0B = lo + kB;
    const uint32_t soA = sbase + (uint32_t)(kA * RD + d4f) * 4u;
    const uint32_t soB = sbase + (uint32_t)(kB * RD + d4f) * 4u;
    const size_t gb = (size_t)(bg * NBL) * RT * RD + d4f;

#define CP_T(tn, gp, tA, tB)                                                    \
    {                                                                           \
        const float* g0 = (gp) + gb;                                            \
        cp16(soA + (uint32_t)((tn) * TS + 0 * BSTR) * 4u,                       \
             g0 + (size_t)(tA) * RD);                                           \
        cp16(soB + (uint32_t)((tn) * TS + 0 * BSTR) * 4u,                       \
             g0 + (size_t)(tB) * RD);                                           \
        cp16(soA + (uint32_t)((tn) * TS + 1 * BSTR) * 4u,                       \
             g0 + (size_t)RT * RD + (size_t)(tA) * RD);                         \
        cp16(soB + (uint32_t)((tn) * TS + 1 * BSTR) * 4u,                       \
             g0 + (size_t)RT * RD + (size_t)(tB) * RD);                         \
    }
    CP_T(0, E,   t1A, t1B)
    CP_T(1, TQ,  t1A, t1B)
    CP_T(2, TPP, t1A, t1B)
    CP_T(3, R,   t0A, t0B)
    CP_T(4, Q,   t0A, t0B)
#undef CP_T

    // bp: 2 b * 16 k = 32 entries, one per thread
    {
        const int b  = tid >> 4;
        const int kk = k0 + (tid & 15);
        const int tb = min(lo + 1 + kk, RT - 1);
        cp4(sbase + (uint32_t)(BPOFF + b * BPSTR + kk) * 4u,
            BPP + (size_t)(bg * NBL + b) * RT + tb);
    }
    cp_commit();
}

__global__ void __launch_bounds__(NTH)
retrace_pass1(const float* __restrict__ Q,
              const float* __restrict__ E,
              const float* __restrict__ TQ,
              const float* __restrict__ TPP,
              const float* __restrict__ R,
              const float* __restrict__ BPP,
              float* __restrict__ out)
{
    extern __shared__ float sm[];
    const int tid = threadIdx.x;
    const int s   = blockIdx.x & (SEG - 1);
    const int bg  = blockIdx.x >> 4;           // 0..1023

    if (blockIdx.x == 0 && tid == 0) out[0] = 0.0f;

    const int lo    = s * SEGLEN;
    const int steps = min(SEGLEN, NJ - lo);    // 32, or 31 for seg 15

    copy_half(sm, tid, bg, lo, 16, E, TQ, TPP, R, Q, BPP);
    copy_half(sm, tid, bg, lo, 0,  E, TQ, TPP, R, Q, BPP);

    const int b_l = tid >> 4;
    const int d   = tid & 15;
    const int rb  = b_l * BSTR + d;
    const int bpb = BPOFF + b_l * BPSTR;

    float q0 = 0.f, P = 1.f, al = 0.f, be = 0.f, de = 0.f;

    cp_wait<1>();
    __syncwarp();

    #pragma unroll 4
    for (int k = steps - 1; k >= 16; --k) {
        const int ro = rb + k * RD;
        const float e   = sm[ro];
        const float tq  = sm[TS + ro];
        const float tpp = sm[2 * TS + ro];
        const float r   = sm[3 * TS + ro];
        const float qv  = sm[4 * TS + ro];
        const float bp  = sm[bpb + k];

        const float c = __expf(fminf(tpp - bp, 0.f));
        const float m = GAMMA * c;
        const float a = fmaf(GAMMA, fmaf(-c, tq, e), r);
        q0 = fmaf(m, q0, a);  P *= m;
        const float u = qv - q0;
        al = fmaf(u, u, al);  be = fmaf(u, P, be);  de = fmaf(P, P, de);
    }

    cp_wait<0>();
    __syncwarp();

    #pragma unroll 4
    for (int k = 15; k >= 0; --k) {
        const int ro = rb + k * RD;
        const float e   = sm[ro];
        const float tq  = sm[TS + ro];
        const float tpp = sm[2 * TS + ro];
        const float r   = sm[3 * TS + ro];
        const float qv  = sm[4 * TS + ro];
        const float bp  = sm[bpb + k];

        const float c = __expf(fminf(tpp - bp, 0.f));
        const float m = GAMMA * c;
        const float a = fmaf(GAMMA, fmaf(-c, tq, e), r);
        q0 = fmaf(m, q0, a);  P *= m;
        const float u = qv - q0;
        al = fmaf(u, u, al);  be = fmaf(u, P, be);  de = fmaf(P, P, de);
    }

    const int chain = (bg * NBL + b_l) * RD + d;
    const size_t idx = (size_t)s * BD + chain;
    g4 [idx] = make_float4(q0, P, be, de);
    gal[idx] = al;
}

// ---------------------------------------------------------------------------
// Pass 2: 8 lanes per chain (sub handles segs {2sub, 2sub+1}); serial fold
// then 3-step width-8 shuffle tree. Compose (X lower-s, Y higher-s):
//   al'' = alY + alX - 2 beX AY + deX AY^2
//   be'' = beY + (beX - deX AY) MY
//   de'' = deY + deX MY^2
//   A''  = AX + MX AY ;  M'' = MX MY
// ---------------------------------------------------------------------------
__global__ void __launch_bounds__(128)
retrace_pass2(const float* __restrict__ TQ, float* __restrict__ out)
{
    const int gid   = blockIdx.x * blockDim.x + threadIdx.x;  // 0..8*BD-1
    const int chain = gid >> 3;
    const int sub   = gid & 7;

    // seed with higher segment of the pair
    size_t idx = (size_t)(sub * 2 + 1) * BD + chain;
    float4 v = g4[idx];
    float A = v.x, M = v.y, be = v.z, de = v.w;
    float al = gal[idx];

    // fold in the lower segment (X = new seg, Y = accumulated)
    {
        idx = (size_t)(sub * 2) * BD + chain;
        const float4 x = g4[idx];
        const float alx = gal[idx];

        const float nal = al + alx - 2.0f * x.z * A + x.w * A * A;
        const float nbe = be + (x.z - x.w * A) * M;
        const float nde = de + x.w * M * M;
        const float nA  = fmaf(x.y, A, x.x);
        const float nM  = x.y * M;
        al = nal; be = nbe; de = nde; A = nA; M = nM;
    }

    // 3-step shuffle compose across the 8 sub-lanes (self = X lower, other = Y higher)
    #pragma unroll
    for (int k = 1; k < 8; k <<= 1) {
        const float oA  = __shfl_down_sync(0xffffffffu, A,  k, 8);
        const float oM  = __shfl_down_sync(0xffffffffu, M,  k, 8);
        const float oal = __shfl_down_sync(0xffffffffu, al, k, 8);
        const float obe = __shfl_down_sync(0xffffffffu, be, k, 8);
        const float ode = __shfl_down_sync(0xffffffffu, de, k, 8);

        const float nal = oal + al - 2.0f * be * oA + de * oA * oA;
        const float nbe = obe + (be - de * oA) * oM;
        const float nde = ode + de * oM * oM;
        const float nA  = fmaf(M, oA, A);
        const float nM  = M * oM;
        al = nal; be = nbe; de = nde; A = nA; M = nM;
    }

    float sum = 0.0f;
    if (sub == 0) {
        const int b = chain >> 4;
        const int d = chain & 15;
        const float carry = TQ[((size_t)b * RT + (RT - 1)) * RD + d];
        sum = fmaf(carry, fmaf(de, carry, -2.0f * be), al);
    }

    #pragma unroll
    for (int o = 16; o > 0; o >>= 1)
        sum += __shfl_down_sync(0xffffffffu, sum, o);

    __shared__ float ws[4];
    const int lane = threadIdx.x & 31;
    const int w    = threadIdx.x >> 5;
    if (lane == 0) ws[w] = sum;
    __syncthreads();

    if (w == 0) {
        float x = (lane < 4) ? ws[lane] : 0.0f;
        #pragma unroll
        for (int o = 2; o > 0; o >>= 1)
            x += __shfl_down_sync(0xffffffffu, x, o);
        if (lane == 0) {
            const float invN = 1.0f / ((float)RB * (float)NJ * (float)RD);
            atomicAdd(out, x * invN);
        }
    }
}

extern "C" void kernel_launch(void* const* d_in, const int* in_sizes, int n_in,
                              void* d_out, int out_size)
{
    const float* Q   = (const float*)d_in[0];
    const float* E   = (const float*)d_in[1];
    const float* TQ  = (const float*)d_in[2];
    const float* R   = (const float*)d_in[3];
    const float* TPP = (const float*)d_in[4];
    const float* BPP = (const float*)d_in[5];
    float* out = (float*)d_out;

    // Pass 1: 1024 b-groups x 16 segments = 16384 blocks of 32 threads
    retrace_pass1<<<NBG * SEG, NTH, SMEM_BYTES>>>(Q, E, TQ, TPP, R, BPP, out);

    // Pass 2: 8 lanes per chain = 262144 threads
    retrace_pass2<<<(BD * 8) / 128, 128>>>(TQ, out);
}

// round 13
// speedup vs baseline: 1.0337x; 1.0337x over previous
#include <cuda_runtime.h>
#include <cstdint>

// Retrace_9844065042706 — affine-segment scan, cp.async staging (split kernels).
// Pass1 (R11 best): block = 4 b x 16 d over a 32-step segment, 64 threads,
// 42.8KB smem -> 5 resident blocks/SM; copy fully strength-reduced.
// Pass2: block = 32 chains x 4 warps; warp w serial-folds segments [4w,4w+4)
// with lane = chain (coalesced 512B record loads), warps compose via smem,
// warp 0 finishes (carry + quadratic + reduce + atomicAdd).

#define RB 2048
#define RT 512
#define RD 16
#define SEG 16
#define SEGLEN 32
#define NJ (RT - 1)            // 511
#define BD (RB * RD)           // 32768 chains
#define NBL 4                  // b's per block (pass1)
#define NTH 64                 // pass1 threads (4 b x 16 d)

// pass1 smem (floats): 5 tensors [4][32][16] (+16 pad per b), then bp [4][33]
#define BSTR  528
#define TS    (NBL * BSTR)     // 2112
#define BPOFF (5 * TS)         // 10560
#define BPSTR 33
#define SMEM_FLOATS (BPOFF + NBL * BPSTR)   // 10692 -> 42768 B
#define SMEM_BYTES  (SMEM_FLOATS * 4)

static constexpr float GAMMA = 0.99f;

// Dense scratch, seg-major (chain-contiguous): 10 MB
__device__ float4 g4 [(size_t)SEG * BD];   // {A, M, beta, delta}
__device__ float  gal[(size_t)SEG * BD];   // alpha

__device__ __forceinline__ void cp16(uint32_t s, const void* g) {
    asm volatile("cp.async.cg.shared.global [%0], [%1], 16;" :: "r"(s), "l"(g));
}
__device__ __forceinline__ void cp4(uint32_t s, const void* g) {
    asm volatile("cp.async.ca.shared.global [%0], [%1], 4;" :: "r"(s), "l"(g));
}
__device__ __forceinline__ void cp_commit() { asm volatile("cp.async.commit_group;"); }
template <int N>
__device__ __forceinline__ void cp_wait() {
    asm volatile("cp.async.wait_group %0;" :: "n"(N));
}
__device__ __forceinline__ uint32_t smem_u32(const void* p) {
    return (uint32_t)__cvta_generic_to_shared(p);
}

// Stage rows [k0, k0+16): thread tid owns chunk (b=j, k=k0+(tid>>2), d4=tid&3).
__device__ __forceinline__ void copy_half(
    float* sm, int tid, int bg, int lo, int k0,
    const float* __restrict__ E, const float* __restrict__ TQ,
    const float* __restrict__ TPP, const float* __restrict__ R,
    const float* __restrict__ Q, const float* __restrict__ BPP)
{
    const uint32_t sbase = smem_u32(sm);
    const int krow = tid >> 2;            // 0..15
    const int d4f  = (tid & 3) * 4;
    const int k    = k0 + krow;
    const int t1   = min(lo + 1 + k, RT - 1);   // rows for E, TQ, TPP
    const int t0   = lo + k;                    // rows for R, Q
    const uint32_t so = sbase + (uint32_t)(k * RD + d4f) * 4u;
    const size_t gb = (size_t)(bg * NBL) * RT * RD + d4f;

#define CP_T(tn, gp, t)                                                        \
    {                                                                          \
        const float* g = (gp) + gb + (size_t)(t) * RD;                         \
        cp16(so + (uint32_t)((tn) * TS + 0 * BSTR) * 4u, g + 0 * RT * RD);     \
        cp16(so + (uint32_t)((tn) * TS + 1 * BSTR) * 4u, g + 1 * RT * RD);     \
        cp16(so + (uint32_t)((tn) * TS + 2 * BSTR) * 4u, g + 2 * RT * RD);     \
        cp16(so + (uint32_t)((tn) * TS + 3 * BSTR) * 4u, g + 3 * RT * RD);     \
    }
    CP_T(0, E,   t1)
    CP_T(1, TQ,  t1)
    CP_T(2, TPP, t1)
    CP_T(3, R,   t0)
    CP_T(4, Q,   t0)
#undef CP_T

    {
        const int b  = tid >> 4;
        const int kk = k0 + (tid & 15);
        const int tb = min(lo + 1 + kk, RT - 1);
        cp4(sbase + (uint32_t)(BPOFF + b * BPSTR + kk) * 4u,
            BPP + (size_t)(bg * NBL + b) * RT + tb);
    }
    cp_commit();
}

__global__ void __launch_bounds__(NTH)
retrace_pass1(const float* __restrict__ Q,
              const float* __restrict__ E,
              const float* __restrict__ TQ,
              const float* __restrict__ TPP,
              const float* __restrict__ R,
              const float* __restrict__ BPP,
              float* __restrict__ out)
{
    extern __shared__ float sm[];
    const int tid = threadIdx.x;
    const int s   = blockIdx.x & (SEG - 1);
    const int bg  = blockIdx.x >> 4;           // 0..511

    if (blockIdx.x == 0 && tid == 0) out[0] = 0.0f;

    const int lo    = s * SEGLEN;
    const int steps = min(SEGLEN, NJ - lo);    // 32, or 31 for seg 15

    copy_half(sm, tid, bg, lo, 16, E, TQ, TPP, R, Q, BPP);
    copy_half(sm, tid, bg, lo, 0,  E, TQ, TPP, R, Q, BPP);

    const int b_l = tid >> 4;
    const int d   = tid & 15;
    const int rb  = b_l * BSTR + d;
    const int bpb = BPOFF + b_l * BPSTR;

    float q0 = 0.f, P = 1.f, al = 0.f, be = 0.f, de = 0.f;

    cp_wait<1>();
    __syncthreads();

    #pragma unroll 4
    for (int k = steps - 1; k >= 16; --k) {
        const int ro = rb + k * RD;
        const float e   = sm[ro];
        const float tq  = sm[TS + ro];
        const float tpp = sm[2 * TS + ro];
        const float r   = sm[3 * TS + ro];
        const float qv  = sm[4 * TS + ro];
        const float bp  = sm[bpb + k];

        const float c = __expf(fminf(tpp - bp, 0.f));
        const float m = GAMMA * c;
        const float a = fmaf(GAMMA, fmaf(-c, tq, e), r);
        q0 = fmaf(m, q0, a);  P *= m;
        const float u = qv - q0;
        al = fmaf(u, u, al);  be = fmaf(u, P, be);  de = fmaf(P, P, de);
    }

    cp_wait<0>();
    __syncthreads();

    #pragma unroll 4
    for (int k = 15; k >= 0; --k) {
        const int ro = rb + k * RD;
        const float e   = sm[ro];
        const float tq  = sm[TS + ro];
        const float tpp = sm[2 * TS + ro];
        const float r   = sm[3 * TS + ro];
        const float qv  = sm[4 * TS + ro];
        const float bp  = sm[bpb + k];

        const float c = __expf(fminf(tpp - bp, 0.f));
        const float m = GAMMA * c;
        const float a = fmaf(GAMMA, fmaf(-c, tq, e), r);
        q0 = fmaf(m, q0, a);  P *= m;
        const float u = qv - q0;
        al = fmaf(u, u, al);  be = fmaf(u, P, be);  de = fmaf(P, P, de);
    }

    const int chain = (bg * NBL + b_l) * RD + d;
    const size_t idx = (size_t)s * BD + chain;
    g4 [idx] = make_float4(q0, P, be, de);
    gal[idx] = al;
}

// ---------------------------------------------------------------------------
// Pass 2: block = 32 chains x 4 warps. Warp w serial-folds segments
// [4w, 4w+4) for its 32 chains (lane = chain low bits -> coalesced loads).
// Warps 1-3 publish records to smem; warp 0 composes (Y from higher warps
// folded down) and finishes. Compose (X lower-s, Y higher-s):
//   al'' = alY + alX - 2 beX AY + deX AY^2
//   be'' = beY + (beX - deX AY) MY
//   de'' = deY + deX MY^2
//   A''  = AX + MX AY ;  M'' = MX MY
// ---------------------------------------------------------------------------
__global__ void __launch_bounds__(128)
retrace_pass2(const float* __restrict__ TQ, float* __restrict__ out)
{
    __shared__ float sA[4][32], sM[4][32], sAL[4][32], sBE[4][32], sDE[4][32];

    const int lane  = threadIdx.x & 31;
    const int w     = threadIdx.x >> 5;          // sub-range = segments [4w, 4w+4)
    const int chain = blockIdx.x * 32 + lane;

    // seed with highest segment of this warp's range
    size_t idx = (size_t)(4 * w + 3) * BD + chain;
    float4 v = g4[idx];
    float A = v.x, M = v.y, be = v.z, de = v.w;
    float al = gal[idx];

    // fold in lower segments (X = new lower seg, Y = accumulated higher run)
    #pragma unroll
    for (int i = 2; i >= 0; --i) {
        idx = (size_t)(4 * w + i) * BD + chain;
        const float4 x = g4[idx];
        const float alx = gal[idx];

        const float nal = al + alx - 2.0f * x.z * A + x.w * A * A;
        const float nbe = be + (x.z - x.w * A) * M;
        const float nde = de + x.w * M * M;
        const float nA  = fmaf(x.y, A, x.x);
        const float nM  = x.y * M;
        al = nal; be = nbe; de = nde; A = nA; M = nM;
    }

    if (w > 0) {
        sA [w][lane] = A;  sM [w][lane] = M;
        sAL[w][lane] = al; sBE[w][lane] = be; sDE[w][lane] = de;
    }
    __syncthreads();

    if (w == 0) {
        // Y = warp3's run, fold X = warp2, warp1, then own registers (warp0).
        float YA = sA[3][lane], YM = sM[3][lane];
        float Yal = sAL[3][lane], Ybe = sBE[3][lane], Yde = sDE[3][lane];

        #pragma unroll
        for (int j = 2; j >= 1; --j) {
            const float xA = sA[j][lane], xM = sM[j][lane];
            const float xal = sAL[j][lane], xbe = sBE[j][lane], xde = sDE[j][lane];

            const float nal = Yal + xal - 2.0f * xbe * YA + xde * YA * YA;
            const float nbe = Ybe + (xbe - xde * YA) * YM;
            const float nde = Yde + xde * YM * YM;
            const float nA  = fmaf(xM, YA, xA);
            const float nM  = xM * YM;
            Yal = nal; Ybe = nbe; Yde = nde; YA = nA; YM = nM;
        }
        // fold own (segments 0-3, the lowest) as X
        {
            const float nal = Yal + al - 2.0f * be * YA + de * YA * YA;
            const float nbe = Ybe + (be - de * YA) * YM;
            const float nde = Yde + de * YM * YM;
            const float nA  = fmaf(M, YA, A);
            Yal = nal; Ybe = nbe; Yde = nde; YA = nA;
        }

        const int b = chain >> 4;
        const int d = chain & 15;
        const float carry = TQ[((size_t)b * RT + (RT - 1)) * RD + d];
        float sum = fmaf(carry, fmaf(Yde, carry, -2.0f * Ybe), Yal);

        #pragma unroll
        for (int o = 16; o > 0; o >>= 1)
            sum += __shfl_down_sync(0xffffffffu, sum, o);

        if (lane == 0) {
            const float invN = 1.0f / ((float)RB * (float)NJ * (float)RD);
            atomicAdd(out, sum * invN);
        }
    }
}

extern "C" void kernel_launch(void* const* d_in, const int* in_sizes, int n_in,
                              void* d_out, int out_size)
{
    const float* Q   = (const float*)d_in[0];
    const float* E   = (const float*)d_in[1];
    const float* TQ  = (const float*)d_in[2];
    const float* R   = (const float*)d_in[3];
    const float* TPP = (const float*)d_in[4];
    const float* BPP = (const float*)d_in[5];
    float* out = (float*)d_out;

    // Pass 1: 512 b-groups x 16 segments = 8192 blocks of 64 threads
    retrace_pass1<<<(RB / NBL) * SEG, NTH, SMEM_BYTES>>>(Q, E, TQ, TPP, R, BPP, out);

    // Pass 2: 1024 blocks x 128 threads (32 chains x 4 warps each)
    retrace_pass2<<<BD / 32, 128>>>(TQ, out);
}